// round 5
// baseline (speedup 1.0000x reference)
#include <cuda_runtime.h>
#include <math.h>

#define MAXDISP 192

// One thread per row. Rows are contiguous 768B; each thread streams its row
// via 48 float4 loads. Warp reads rows t..t+31 (contiguous 24KB), every 128B
// line fully consumed by one thread across 8 consecutive iterations -> L1
// hit for 7/8 accesses, DRAM sectors fully utilized.
__global__ __launch_bounds__(256)
void disp_reg_kernel(const float* __restrict__ cost,
                     float* __restrict__ out,
                     int nrows)
{
    const int row = blockIdx.x * blockDim.x + threadIdx.x;
    if (row >= nrows) return;

    const float4* __restrict__ p =
        (const float4*)(cost + (size_t)row * MAXDISP);

    // Exact running top-2 with indices. Strict '>' keeps the FIRST (lowest
    // index) occurrence on ties -> matches jax.lax.top_k tie-break exactly.
    float v1 = -INFINITY, v2 = -INFINITY;
    int   i1 = 0,         i2 = 0;

#pragma unroll 8
    for (int q = 0; q < MAXDISP / 4; q++) {
        const float4 d = p[q];
        const int c = q * 4;

        {
            const float x = d.x; const int cc = c + 0;
            const bool g1 = x > v1, g2 = x > v2;
            i2 = g1 ? i1 : (g2 ? cc : i2);
            v2 = g1 ? v1 : (g2 ? x  : v2);
            i1 = g1 ? cc : i1;
            v1 = g1 ? x  : v1;
        }
        {
            const float x = d.y; const int cc = c + 1;
            const bool g1 = x > v1, g2 = x > v2;
            i2 = g1 ? i1 : (g2 ? cc : i2);
            v2 = g1 ? v1 : (g2 ? x  : v2);
            i1 = g1 ? cc : i1;
            v1 = g1 ? x  : v1;
        }
        {
            const float x = d.z; const int cc = c + 2;
            const bool g1 = x > v1, g2 = x > v2;
            i2 = g1 ? i1 : (g2 ? cc : i2);
            v2 = g1 ? v1 : (g2 ? x  : v2);
            i1 = g1 ? cc : i1;
            v1 = g1 ? x  : v1;
        }
        {
            const float x = d.w; const int cc = c + 3;
            const bool g1 = x > v1, g2 = x > v2;
            i2 = g1 ? i1 : (g2 ? cc : i2);
            v2 = g1 ? v1 : (g2 ? x  : v2);
            i1 = g1 ? cc : i1;
            v1 = g1 ? x  : v1;
        }
    }

    // Same epilogue formula as the known-passing R3 kernel (exact values).
    const float pr = 1.0f / (1.0f + __expf(v2 - v1));
    out[row] = (float)i1 * pr + (float)i2 * (1.0f - pr);
}

extern "C" void kernel_launch(void* const* d_in, const int* in_sizes, int n_in,
                              void* d_out, int out_size)
{
    const float* cost = (const float*)d_in[0];
    float* out = (float*)d_out;

    const int nrows = in_sizes[0] / MAXDISP;   // 4 * 131072 = 524288

    const int threads = 256;
    const int blocks = (nrows + threads - 1) / threads;   // 2048

    disp_reg_kernel<<<blocks, threads>>>(cost, out, nrows);
}

// round 6
// speedup vs baseline: 1.2384x; 1.2384x over previous
#include <cuda_runtime.h>
#include <math.h>

#define MAXDISP 192
#define RPW 4   // rows per warp

// Bijective monotone map: float bits -> uint32, uint compare == float compare.
__device__ __forceinline__ unsigned f2k(float f) {
    unsigned b = __float_as_uint(f);
    return b ^ (unsigned)(((int)b >> 31) | 0x80000000);
}
__device__ __forceinline__ float k2f(unsigned k) {
    unsigned t = (unsigned)((int)k >> 31);         // all-ones if orig positive
    return __uint_as_float(k ^ (~t | 0x80000000u));
}

__global__ __launch_bounds__(256, 5)
void disp_reg_kernel(const float* __restrict__ cost,
                     float* __restrict__ out,
                     int nrows)
{
    const int warp = (blockIdx.x * blockDim.x + threadIdx.x) >> 5;
    const int lane = threadIdx.x & 31;
    const int row0 = warp * RPW;
    if (row0 >= nrows) return;

    const float* base = cost + (size_t)row0 * MAXDISP;
    const int b0 = lane * 2;

    // Front-batch all 12 coalesced 64-bit loads (4 rows x 3 vectors) for MLP.
    float2 d[RPW][3];
#pragma unroll
    for (int r = 0; r < RPW; r++) {
#pragma unroll
        for (int k = 0; k < 3; k++) {
            d[r][k] = *(const float2*)(base + r * MAXDISP + b0 + 64 * k);
        }
    }

    // Per-row results stashed in lane r's registers.
    float    rva = 0.0f, rvb = 0.0f;
    unsigned ri1 = 0,    ri2 = 0;

#pragma unroll
    for (int r = 0; r < RPW; r++) {
        const float x[6]     = { d[r][0].x, d[r][0].y, d[r][1].x,
                                 d[r][1].y, d[r][2].x, d[r][2].y };
        const unsigned id[6] = { (unsigned)b0,        (unsigned)(b0 + 1),
                                 (unsigned)(b0 + 64), (unsigned)(b0 + 65),
                                 (unsigned)(b0 + 128),(unsigned)(b0 + 129) };

        // Exact branchless local top-2; strict '>' over ascending columns
        // keeps FIRST (lowest column) on exact ties -> top_k tie-break.
        float    v1 = x[0], v2 = -INFINITY;
        unsigned i1 = id[0], i2 = 0;
#pragma unroll
        for (int k = 1; k < 6; k++) {
            const bool g1 = x[k] > v1;
            const bool g2 = x[k] > v2;
            i2 = g1 ? i1 : (g2 ? id[k] : i2);
            v2 = g1 ? v1 : (g2 ? x[k]  : v2);
            i1 = g1 ? id[k] : i1;
            v1 = g1 ? x[k]  : v1;
        }

        // Exact warp top-2 with lowest-COLUMN tie-break (no ballot/shfl).
        const unsigned k1  = f2k(v1);                       // exact, bijective
        const unsigned t1  = __reduce_max_sync(0xFFFFFFFFu, k1);
        const bool     e1  = (k1 == t1);
        const unsigned gi1 = __reduce_min_sync(0xFFFFFFFFu, e1 ? i1 : 0xFFFFu);

        // Only the lane owning column gi1 substitutes its local second;
        // duplicate-value lanes keep v1 so exact ties propagate to rank 2.
        const bool     own  = e1 && (i1 == gi1);
        const float    cnd  = own ? v2 : v1;
        const unsigned ci   = own ? i2 : i1;
        const unsigned k2   = f2k(cnd);
        const unsigned t2   = __reduce_max_sync(0xFFFFFFFFu, k2);
        const unsigned gi2  = __reduce_min_sync(0xFFFFFFFFu,
                                                (k2 == t2) ? ci : 0xFFFFu);

        if (lane == r) { rva = k2f(t1); rvb = k2f(t2); ri1 = gi1; ri2 = gi2; }
    }

    // One consolidated epilogue: lanes 0..RPW-1 finalize their rows
    // (RPW parallel exp's, one coalesced 16B store per warp).
    if (lane < RPW && (row0 + lane) < nrows) {
        const float p = 1.0f / (1.0f + __expf(rvb - rva));
        out[row0 + lane] = (float)ri1 * p + (float)ri2 * (1.0f - p);
    }
}

extern "C" void kernel_launch(void* const* d_in, const int* in_sizes, int n_in,
                              void* d_out, int out_size)
{
    const float* cost = (const float*)d_in[0];
    float* out = (float*)d_out;

    const int nrows = in_sizes[0] / MAXDISP;   // 4 * 131072 = 524288

    const int threads = 256;                   // 8 warps/block, 32 rows/block
    const int rows_per_block = (threads / 32) * RPW;
    const int blocks = (nrows + rows_per_block - 1) / rows_per_block;

    disp_reg_kernel<<<blocks, threads>>>(cost, out, nrows);
}

// round 8
// speedup vs baseline: 1.4408x; 1.1634x over previous
#include <cuda_runtime.h>
#include <math.h>

#define MAXDISP 192
#define RPW 4   // rows per warp (processed in two batches of 2)

// Bijective monotone map: float bits -> uint32, uint compare == float compare.
__device__ __forceinline__ unsigned f2k(float f) {
    unsigned b = __float_as_uint(f);
    return b ^ (unsigned)(((int)b >> 31) | 0x80000000);
}
__device__ __forceinline__ float k2f(unsigned k) {
    unsigned t = (unsigned)((int)k >> 31);         // all-ones if orig positive
    return __uint_as_float(k ^ (~t | 0x80000000u));
}

// slot code s in 0..5 -> column = b0 + (s&1) + (s>>1)*64
__device__ __forceinline__ unsigned decode_col(unsigned b0, unsigned s) {
    return b0 + (s & 1u) + ((s >> 1) << 6);
}

struct RowRes { unsigned ka, kb, i1, i2; };

// Exact top-2 of one row slice (6 values) + exact warp top-2 with
// lowest-column tie-break. All tie paths keep the earlier column.
__device__ __forceinline__ RowRes row_top2(const float2* dd, unsigned b0) {
    const float x0 = dd[0].x, x1 = dd[0].y;
    const float x2 = dd[1].x, x3 = dd[1].y;
    const float x4 = dd[2].x, x5 = dd[2].y;

    // Column-ordered pairs; strict '>' -> ties keep earlier slot.
    const bool g0 = x1 > x0;
    const float h0 = fmaxf(x0, x1), l0 = fminf(x0, x1);
    const unsigned s0h = g0 ? 1u : 0u, s0l = 1u - s0h;

    const bool g1 = x3 > x2;
    const float h1 = fmaxf(x2, x3), l1 = fminf(x2, x3);
    const unsigned s1h = g1 ? 3u : 2u, s1l = 5u - s1h;

    const bool g2 = x5 > x4;
    const float h2 = fmaxf(x4, x5), l2 = fminf(x4, x5);
    const unsigned s2h = g2 ? 5u : 4u, s2l = 9u - s2h;

    // merge(pair0, pair1): A = earlier columns; ties -> A side.
    float v1, v2; unsigned c1, c2;
    {
        const bool m = h1 > h0;
        v1 = fmaxf(h0, h1);
        c1 = m ? s1h : s0h;
        const float    sa = m ? h0  : l0;
        const unsigned ca = m ? s0h : s0l;
        const float    sb = m ? l1  : h1;
        const unsigned cb = m ? s1l : s1h;
        const bool h = sb > sa;
        v2 = fmaxf(sa, sb);
        c2 = h ? cb : ca;
    }
    // merge(M, pair2)
    {
        const bool m = h2 > v1;
        const float    nv1 = fmaxf(v1, h2);
        const unsigned nc1 = m ? s2h : c1;
        const float    sa = m ? v1 : v2;
        const unsigned ca = m ? c1 : c2;
        const float    sb = m ? l2  : h2;
        const unsigned cb = m ? s2l : s2h;
        const bool h = sb > sa;
        v2 = fmaxf(sa, sb);
        c2 = h ? cb : ca;
        v1 = nv1; c1 = nc1;
    }

    // Warp top-1 (exact value via bijective key).
    const unsigned k1 = f2k(v1);
    const unsigned t1 = __reduce_max_sync(0xFFFFFFFFu, k1);
    const unsigned col1 = decode_col(b0, c1);
    const unsigned gi1 = __reduce_min_sync(0xFFFFFFFFu,
                                           (k1 == t1) ? col1 : 0xFFFFu);

    // Columns are unique across lanes, so col1==gi1 identifies the single
    // owner; tied duplicate lanes keep v1 so exact ties reach rank 2.
    const bool own = (col1 == gi1);
    const float    cnd = own ? v2 : v1;
    const unsigned cc  = own ? c2 : c1;
    const unsigned k2 = f2k(cnd);
    const unsigned t2 = __reduce_max_sync(0xFFFFFFFFu, k2);
    const unsigned col2 = decode_col(b0, cc);
    const unsigned gi2 = __reduce_min_sync(0xFFFFFFFFu,
                                           (k2 == t2) ? col2 : 0xFFFFu);

    RowRes res; res.ka = t1; res.kb = t2; res.i1 = gi1; res.i2 = gi2;
    return res;
}

__global__ __launch_bounds__(256, 6)
void disp_reg_kernel(const float* __restrict__ cost,
                     float* __restrict__ out,
                     int nrows)
{
    const int warp = (blockIdx.x * blockDim.x + threadIdx.x) >> 5;
    const int lane = threadIdx.x & 31;
    const int row0 = warp * RPW;
    if (row0 >= nrows) return;

    const float* base = cost + (size_t)row0 * MAXDISP;
    const unsigned b0 = (unsigned)(lane * 2);

    // Per-row results stashed in lane r's registers (as keys).
    unsigned rka = 0, rkb = 0, ri1 = 0, ri2 = 0;

    // Two batches of 2 rows: 6 front-batched LDG.64 per batch, 12 live
    // data regs instead of 24 -> fits the 40-reg budget for 6 blocks/SM.
#pragma unroll
    for (int bat = 0; bat < RPW / 2; bat++) {
        float2 d[2][3];
#pragma unroll
        for (int r = 0; r < 2; r++) {
#pragma unroll
            for (int k = 0; k < 3; k++) {
                d[r][k] = *(const float2*)(base + (bat * 2 + r) * MAXDISP
                                           + b0 + 64 * k);
            }
        }
#pragma unroll
        for (int r = 0; r < 2; r++) {
            const RowRes res = row_top2(d[r], b0);
            const int rr = bat * 2 + r;
            if (lane == rr) { rka = res.ka; rkb = res.kb;
                              ri1 = res.i1; ri2 = res.i2; }
        }
    }

    // Consolidated epilogue: lanes 0..RPW-1 finalize their rows
    // (RPW parallel exp's, one coalesced 16B store per warp).
    if (lane < RPW && (row0 + lane) < nrows) {
        const float va = k2f(rka);
        const float vb = k2f(rkb);
        const float p = 1.0f / (1.0f + __expf(vb - va));
        out[row0 + lane] = (float)ri1 * p + (float)ri2 * (1.0f - p);
    }
}

extern "C" void kernel_launch(void* const* d_in, const int* in_sizes, int n_in,
                              void* d_out, int out_size)
{
    const float* cost = (const float*)d_in[0];
    float* out = (float*)d_out;

    const int nrows = in_sizes[0] / MAXDISP;   // 4 * 131072 = 524288

    const int threads = 256;                   // 8 warps/block, 32 rows/block
    const int rows_per_block = (threads / 32) * RPW;
    const int blocks = (nrows + rows_per_block - 1) / rows_per_block;

    disp_reg_kernel<<<blocks, threads>>>(cost, out, nrows);
}